// round 5
// baseline (speedup 1.0000x reference)
#include <cuda_runtime.h>

#define HID   16
#define INS   64
#define SEQT  12
#define G4    64   // 4*HID gates

// ---- packed f32x2 helpers (Blackwell dual-FP32 pipe, PTX-only) ----
// Fallback to scalar fmaf pairs if not compiling for sm_100+ so the file
// always compiles and runs correctly.
#if defined(__CUDA_ARCH__) && (__CUDA_ARCH__ >= 1000) && !defined(NO_F32X2)
#define HAVE_F32X2 1
#else
#define HAVE_F32X2 0
#endif

struct pak2 {
#if HAVE_F32X2
    unsigned long long v;
#else
    float a, b;
#endif
};

__device__ __forceinline__ pak2 pk2(float x, float y) {
    pak2 r;
#if HAVE_F32X2
    asm("mov.b64 %0, {%1, %2};" : "=l"(r.v) : "f"(x), "f"(y));
#else
    r.a = x; r.b = y;
#endif
    return r;
}
__device__ __forceinline__ void upk2(pak2 v, float& x, float& y) {
#if HAVE_F32X2
    asm("mov.b64 {%0, %1}, %2;" : "=f"(x), "=f"(y) : "l"(v.v));
#else
    x = v.a; y = v.b;
#endif
}
__device__ __forceinline__ void ffma2(pak2& d, pak2 a, pak2 b) {
#if HAVE_F32X2
    asm("fma.rn.f32x2 %0, %1, %2, %0;" : "+l"(d.v) : "l"(a.v), "l"(b.v));
#else
    d.a = fmaf(a.a, b.a, d.a);
    d.b = fmaf(a.b, b.b, d.b);
#endif
}
__device__ __forceinline__ pak2 ld2(const float* p) {
    // p must be 8B-aligned; single LDS.64 / LDG.64
    float2 t = *(const float2*)p;
    return pk2(t.x, t.y);
}

// ---- overflow-safe fast activations (err ~1e-6, well under 1e-3 budget) ----
__device__ __forceinline__ float fast_sig(float x) {
    float e = __expf(-x);                       // x->-inf: e=inf -> 1/inf = 0  OK
    return __fdividef(1.0f, 1.0f + e);
}
__device__ __forceinline__ float fast_tanh(float x) {
    float e = __expf(2.0f * x);                 // x large: e=inf -> 1-0 = 1   OK
    return 1.0f - __fdividef(2.0f, e + 1.0f);   // x->-inf: e=0   -> 1-2 = -1  OK
}

__global__ __launch_bounds__(256)
void lstm_head_kernel(const float* __restrict__ x,
                      const float* __restrict__ Wih,   // [64 gates, 64 in]
                      const float* __restrict__ Whh,   // [64 gates, 16 hid]
                      const float* __restrict__ bih,
                      const float* __restrict__ bhh,
                      const float* __restrict__ fcw,   // [1, 16]
                      const float* __restrict__ fcb,   // [1]
                      float* __restrict__ out,
                      int batch)
{
    // Weights transposed to [k][g] so the inner g-loop is contiguous ->
    // vector LDS broadcast (all lanes same address, conflict-free).
    __shared__ __align__(16) float s_wih[INS * G4];  // [i][g]
    __shared__ __align__(16) float s_whh[HID * G4];  // [j][g]
    __shared__ __align__(16) float s_b[G4];
    __shared__ __align__(16) float s_fcw[HID];
    __shared__ float s_fcb;

    const int tid = threadIdx.x;
    for (int idx = tid; idx < INS * G4; idx += blockDim.x) {
        int i = idx >> 6, g = idx & 63;
        s_wih[idx] = Wih[g * INS + i];
    }
    for (int idx = tid; idx < HID * G4; idx += blockDim.x) {
        int j = idx >> 6, g = idx & 63;
        s_whh[idx] = Whh[g * HID + j];
    }
    if (tid < G4)  s_b[tid]   = bih[tid] + bhh[tid];
    if (tid < HID) s_fcw[tid] = fcw[tid];
    if (tid == 0)  s_fcb      = fcb[0];
    __syncthreads();

    const int b = blockIdx.x * blockDim.x + tid;
    if (b >= batch) return;

    float h[HID], c[HID];
#pragma unroll
    for (int j = 0; j < HID; j++) { h[j] = 0.0f; c[j] = 0.0f; }

    const float4* xr = (const float4*)(x + (size_t)b * SEQT * INS);

#pragma unroll 1
    for (int t = 0; t < SEQT; t++) {
        // 32 packed accumulators = 64 gate pre-activations, init with bias
        pak2 acc[32];
#pragma unroll
        for (int k = 0; k < 32; k++) acc[k] = ld2(s_b + 2 * k);

        // x contribution: gates[g] += sum_i x[t][i] * Wih[g][i]
        // Prefetch one float4 ahead so the LDG wait overlaps the FMA burst.
        float4 xq = __ldg(&xr[t * 16]);
#pragma unroll 4
        for (int i4 = 0; i4 < 16; i4++) {
            float4 xcur = xq;
            if (i4 < 15) xq = __ldg(&xr[t * 16 + i4 + 1]);
            float xs[4] = {xcur.x, xcur.y, xcur.z, xcur.w};
#pragma unroll
            for (int s = 0; s < 4; s++) {
                pak2 x2 = pk2(xs[s], xs[s]);
                const float* w = s_wih + ((i4 << 2) + s) * G4;
#pragma unroll
                for (int k = 0; k < 32; k++) {
                    pak2 wv = ld2(w + 2 * k);       // shared broadcast
                    ffma2(acc[k], wv, x2);
                }
            }
        }

        // recurrent contribution: gates[g] += sum_j h[j] * Whh[g][j]
#pragma unroll
        for (int j = 0; j < HID; j++) {
            pak2 h2 = pk2(h[j], h[j]);
            const float* w = s_whh + j * G4;
#pragma unroll
            for (int k = 0; k < 32; k++) {
                pak2 wv = ld2(w + 2 * k);
                ffma2(acc[k], wv, h2);
            }
        }

        // activations + state update; gate order i,f,g,o in 16-blocks.
        // acc[k] holds gates (2k, 2k+1): i-gates in acc[0..7], f in acc[8..15],
        // g in acc[16..23], o in acc[24..31].
#pragma unroll
        for (int j2 = 0; j2 < 8; j2++) {
            float i0, i1, f0, f1, g0, g1, o0, o1;
            upk2(acc[j2],      i0, i1);
            upk2(acc[8 + j2],  f0, f1);
            upk2(acc[16 + j2], g0, g1);
            upk2(acc[24 + j2], o0, o1);
            {
                int j = 2 * j2;
                float ig = fast_sig(i0), fg = fast_sig(f0);
                float gg = fast_tanh(g0), og = fast_sig(o0);
                float cn = fg * c[j] + ig * gg;
                c[j] = cn;
                h[j] = og * fast_tanh(cn);
            }
            {
                int j = 2 * j2 + 1;
                float ig = fast_sig(i1), fg = fast_sig(f1);
                float gg = fast_tanh(g1), og = fast_sig(o1);
                float cn = fg * c[j] + ig * gg;
                c[j] = cn;
                h[j] = og * fast_tanh(cn);
            }
        }
    }

    // fc head: out[b] = h . fc_w + fc_b
    float o = s_fcb;
#pragma unroll
    for (int j = 0; j < HID; j++) o = fmaf(h[j], s_fcw[j], o);
    out[b] = o;
}

extern "C" void kernel_launch(void* const* d_in, const int* in_sizes, int n_in,
                              void* d_out, int out_size)
{
    const float* x    = (const float*)d_in[0];
    const float* Wih  = (const float*)d_in[1];
    const float* Whh  = (const float*)d_in[2];
    const float* bih  = (const float*)d_in[3];
    const float* bhh  = (const float*)d_in[4];
    const float* fcw  = (const float*)d_in[5];
    const float* fcb  = (const float*)d_in[6];
    float* out = (float*)d_out;

    int batch = in_sizes[0] / (SEQT * INS);
    int threads = 256;
    int blocks = (batch + threads - 1) / threads;
    lstm_head_kernel<<<blocks, threads>>>(x, Wih, Whh, bih, bhh, fcw, fcb,
                                          out, batch);
}

// round 6
// speedup vs baseline: 1.5414x; 1.5414x over previous
#include <cuda_runtime.h>

#define HID   16
#define INS   64
#define SEQT  12
#define G4    64
#define WROW  36   // padded row stride (floats) for a 32-gate subset row (144B)

// ---- packed f32x2 helpers (Blackwell dual-FP32 pipe) with scalar fallback ----
#if defined(__CUDA_ARCH__) && (__CUDA_ARCH__ >= 1000) && !defined(NO_F32X2)
#define HAVE_F32X2 1
#else
#define HAVE_F32X2 0
#endif

struct pak2 {
#if HAVE_F32X2
    unsigned long long v;
#else
    float a, b;
#endif
};

__device__ __forceinline__ pak2 pk2(float x, float y) {
    pak2 r;
#if HAVE_F32X2
    asm("mov.b64 %0, {%1, %2};" : "=l"(r.v) : "f"(x), "f"(y));
#else
    r.a = x; r.b = y;
#endif
    return r;
}
__device__ __forceinline__ void upk2(pak2 v, float& x, float& y) {
#if HAVE_F32X2
    asm("mov.b64 {%0, %1}, %2;" : "=f"(x), "=f"(y) : "l"(v.v));
#else
    x = v.a; y = v.b;
#endif
}
__device__ __forceinline__ void ffma2(pak2& d, pak2 a, pak2 b) {
#if HAVE_F32X2
    asm("fma.rn.f32x2 %0, %1, %2, %0;" : "+l"(d.v) : "l"(a.v), "l"(b.v));
#else
    d.a = fmaf(a.a, b.a, d.a);
    d.b = fmaf(a.b, b.b, d.b);
#endif
}

// ---- overflow-safe fast activations (err ~1e-6, budget is 1e-3) ----
__device__ __forceinline__ float fast_sig(float x) {
    float e = __expf(-x);
    return __fdividef(1.0f, 1.0f + e);
}
__device__ __forceinline__ float fast_tanh(float x) {
    float e = __expf(2.0f * x);
    return 1.0f - __fdividef(2.0f, e + 1.0f);
}

// Each thread: 32 gates (one 8-unit half of all 4 gate types) x 2 batch elems.
// Lane pair (2p, 2p+1) covers both halves of batch elements (b0, b1).
// Weight LDS.128 is reused by 4 FFMA2 (2 accs x 2 elements) -> 8x fewer
// shared wavefronts than the 688us LDS.64 version.
__global__ __launch_bounds__(128)
void lstm_head_kernel(const float* __restrict__ x,
                      const float* __restrict__ Wih,   // [64 gates, 64 in]
                      const float* __restrict__ Whh,   // [64 gates, 16 hid]
                      const float* __restrict__ bih,
                      const float* __restrict__ bhh,
                      const float* __restrict__ fcw,   // [1, 16]
                      const float* __restrict__ fcb,   // [1]
                      float* __restrict__ out,
                      int batch)
{
    // layout: s_wih[(i*2 + uh)*WROW + pos], pos = q*8 + (unit&7), q = gate type.
    // The 144B parity stride puts the two lanes' rows in disjoint bank groups.
    __shared__ __align__(16) float s_wih[INS * 2 * WROW];  // 18.4 KB
    __shared__ __align__(16) float s_whh[HID * 2 * WROW];  // 4.6 KB
    __shared__ __align__(16) float s_b[2 * WROW];
    __shared__ __align__(16) float s_fcw[HID];
    __shared__ float s_fcb;

    const int tid = threadIdx.x;
    for (int idx = tid; idx < G4 * INS; idx += blockDim.x) {
        int g = idx >> 6, i = idx & 63;
        int q = g >> 4, u = g & 15;
        int uh = u >> 3, pos = q * 8 + (u & 7);
        s_wih[(i * 2 + uh) * WROW + pos] = Wih[g * INS + i];
    }
    for (int idx = tid; idx < G4 * HID; idx += blockDim.x) {
        int g = idx >> 4, j = idx & 15;
        int q = g >> 4, u = g & 15;
        int uh = u >> 3, pos = q * 8 + (u & 7);
        s_whh[(j * 2 + uh) * WROW + pos] = Whh[g * HID + j];
    }
    if (tid < G4) {
        int g = tid;
        int q = g >> 4, u = g & 15;
        int uh = u >> 3, pos = q * 8 + (u & 7);
        s_b[uh * WROW + pos] = bih[g] + bhh[g];
    }
    if (tid < HID) s_fcw[tid] = fcw[tid];
    if (tid == 0)  s_fcb      = fcb[0];
    __syncthreads();

    const int gid = blockIdx.x * blockDim.x + tid;
    const int uh  = gid & 1;             // my unit-half (units uh*8 .. uh*8+7)
    const int b0  = (gid >> 1) * 2;      // pair's batch elements b0, b0+1
    if (b0 >= batch) return;             // batch is even; full warps in practice

    float h0[8], c0[8], h1[8], c1[8];
#pragma unroll
    for (int k = 0; k < 8; k++) { h0[k] = c0[k] = h1[k] = c1[k] = 0.0f; }

    const float4* xr0 = (const float4*)(x + (size_t)b0 * SEQT * INS);
    const float4* xr1 = (const float4*)(x + ((size_t)b0 + 1) * SEQT * INS);
    const float* bb = s_b + uh * WROW;

#pragma unroll 1
    for (int t = 0; t < SEQT; t++) {
        // 16 pak2 per element = 32 gate pre-activations, init with bias
        pak2 a0[16], a1[16];
#pragma unroll
        for (int k = 0; k < 16; k++) {
            float2 bv = *(const float2*)(bb + 2 * k);
            a0[k] = pk2(bv.x, bv.y);
            a1[k] = a0[k];
        }

        // ---- x contribution, prefetched one float4 ahead per element ----
        float4 p0 = __ldg(&xr0[t * 16]);
        float4 p1 = __ldg(&xr1[t * 16]);
#pragma unroll 4
        for (int i4 = 0; i4 < 16; i4++) {
            float4 q0 = p0, q1 = p1;
            if (i4 < 15) {
                p0 = __ldg(&xr0[t * 16 + i4 + 1]);
                p1 = __ldg(&xr1[t * 16 + i4 + 1]);
            }
            float xs0[4] = {q0.x, q0.y, q0.z, q0.w};
            float xs1[4] = {q1.x, q1.y, q1.z, q1.w};
#pragma unroll
            for (int s = 0; s < 4; s++) {
                int i = (i4 << 2) + s;
                const float* w = s_wih + (i * 2 + uh) * WROW;
                pak2 xa = pk2(xs0[s], xs0[s]);
                pak2 xb = pk2(xs1[s], xs1[s]);
#pragma unroll
                for (int k = 0; k < 8; k++) {
                    float4 wq = *(const float4*)(w + 4 * k);   // LDS.128
                    pak2 wlo = pk2(wq.x, wq.y);
                    pak2 whi = pk2(wq.z, wq.w);
                    ffma2(a0[2 * k],     wlo, xa);
                    ffma2(a0[2 * k + 1], whi, xa);
                    ffma2(a1[2 * k],     wlo, xb);
                    ffma2(a1[2 * k + 1], whi, xb);
                }
            }
        }

        // ---- recurrent contribution: need full h; pair-exchange via shfl ----
#pragma unroll
        for (int k = 0; k < 8; k++) {
            float m0 = h0[k], m1 = h1[k];
            float th0 = __shfl_xor_sync(0xffffffffu, m0, 1);
            float th1 = __shfl_xor_sync(0xffffffffu, m1, 1);
            // value of low-half unit k and high-half unit 8+k, both elements
            float lo0 = uh ? th0 : m0,  hi0 = uh ? m0 : th0;
            float lo1 = uh ? th1 : m1,  hi1 = uh ? m1 : th1;
            {   // j = k
                const float* w = s_whh + (k * 2 + uh) * WROW;
                pak2 ha = pk2(lo0, lo0), hb = pk2(lo1, lo1);
#pragma unroll
                for (int kk = 0; kk < 8; kk++) {
                    float4 wq = *(const float4*)(w + 4 * kk);
                    pak2 wlo = pk2(wq.x, wq.y);
                    pak2 whi = pk2(wq.z, wq.w);
                    ffma2(a0[2 * kk],     wlo, ha);
                    ffma2(a0[2 * kk + 1], whi, ha);
                    ffma2(a1[2 * kk],     wlo, hb);
                    ffma2(a1[2 * kk + 1], whi, hb);
                }
            }
            {   // j = 8 + k
                const float* w = s_whh + ((8 + k) * 2 + uh) * WROW;
                pak2 ha = pk2(hi0, hi0), hb = pk2(hi1, hi1);
#pragma unroll
                for (int kk = 0; kk < 8; kk++) {
                    float4 wq = *(const float4*)(w + 4 * kk);
                    pak2 wlo = pk2(wq.x, wq.y);
                    pak2 whi = pk2(wq.z, wq.w);
                    ffma2(a0[2 * kk],     wlo, ha);
                    ffma2(a0[2 * kk + 1], whi, ha);
                    ffma2(a1[2 * kk],     wlo, hb);
                    ffma2(a1[2 * kk + 1], whi, hb);
                }
            }
        }

        // ---- activations + state update (pos = q*8+k; pak2 = q*4 + k/2) ----
#pragma unroll
        for (int k = 0; k < 8; k++) {
            const int m = k >> 1;
            float v0, v1;
            // element 0
            float gi, gf, gg_, go;
            upk2(a0[m],      v0, v1); gi  = (k & 1) ? v1 : v0;
            upk2(a0[4 + m],  v0, v1); gf  = (k & 1) ? v1 : v0;
            upk2(a0[8 + m],  v0, v1); gg_ = (k & 1) ? v1 : v0;
            upk2(a0[12 + m], v0, v1); go  = (k & 1) ? v1 : v0;
            {
                float ig = fast_sig(gi), fg = fast_sig(gf);
                float g2 = fast_tanh(gg_), og = fast_sig(go);
                float cn = fg * c0[k] + ig * g2;
                c0[k] = cn;
                h0[k] = og * fast_tanh(cn);
            }
            // element 1
            upk2(a1[m],      v0, v1); gi  = (k & 1) ? v1 : v0;
            upk2(a1[4 + m],  v0, v1); gf  = (k & 1) ? v1 : v0;
            upk2(a1[8 + m],  v0, v1); gg_ = (k & 1) ? v1 : v0;
            upk2(a1[12 + m], v0, v1); go  = (k & 1) ? v1 : v0;
            {
                float ig = fast_sig(gi), fg = fast_sig(gf);
                float g2 = fast_tanh(gg_), og = fast_sig(go);
                float cn = fg * c1[k] + ig * g2;
                c1[k] = cn;
                h1[k] = og * fast_tanh(cn);
            }
        }
    }

    // ---- fc head: partial dot over my units, pair-sum via shfl ----
    float p0 = 0.0f, p1 = 0.0f;
#pragma unroll
    for (int k = 0; k < 8; k++) {
        float w = s_fcw[uh * 8 + k];
        p0 = fmaf(h0[k], w, p0);
        p1 = fmaf(h1[k], w, p1);
    }
    p0 += __shfl_xor_sync(0xffffffffu, p0, 1);
    p1 += __shfl_xor_sync(0xffffffffu, p1, 1);
    // lane uh writes batch element b0+uh (warp writes are fully coalesced)
    out[b0 + uh] = (uh ? p1 : p0) + s_fcb;
}

extern "C" void kernel_launch(void* const* d_in, const int* in_sizes, int n_in,
                              void* d_out, int out_size)
{
    const float* x    = (const float*)d_in[0];
    const float* Wih  = (const float*)d_in[1];
    const float* Whh  = (const float*)d_in[2];
    const float* bih  = (const float*)d_in[3];
    const float* bhh  = (const float*)d_in[4];
    const float* fcw  = (const float*)d_in[5];
    const float* fcb  = (const float*)d_in[6];
    float* out = (float*)d_out;

    int batch = in_sizes[0] / (SEQT * INS);
    int threads = 128;                       // one thread per (element, half)
    int blocks = (batch + threads - 1) / threads;
    lstm_head_kernel<<<blocks, threads>>>(x, Wih, Whh, bih, bhh, fcw, fcb,
                                          out, batch);
}

// round 10
// speedup vs baseline: 3.3490x; 2.1727x over previous
#include <cuda_runtime.h>
#include <cstdint>

#define HID    16
#define INS    64
#define SEQT   12
#define TILE_B 128
#define XSTRIDE 144            // padded bf16 row stride (bytes): conflict-free

// ---- dynamic smem layout (bytes) ----
#define SM_WIH_HI 0            // 64 rows x 144B  (Wih hi bf16)
#define SM_WIH_LO 9216         // 64 rows x 144B
#define SM_X_HI   18432        // 128 rows x 144B (x hi)
#define SM_X_LO   36864        // 128 rows x 144B
#define SM_WHH    55296        // [64][16] f32
#define SM_BIAS   59392        // 64 f32
#define SM_FCW    59648        // 16 f32
#define SM_FCB    59712
#define SM_TOTAL  59776

__device__ __forceinline__ uint32_t s2u(const void* p) {
    uint32_t a;
    asm("{ .reg .u64 t; cvta.to.shared.u64 t, %1; cvt.u32.u64 %0, t; }"
        : "=r"(a) : "l"(p));
    return a;
}
// split-bf16: (x0,x1) -> hi pack {lo16=x0,hi16=x1} and residual lo pack
__device__ __forceinline__ void cvt2(uint32_t& hp, uint32_t& lp, float x0, float x1) {
    asm("cvt.rn.bf16x2.f32 %0, %1, %2;" : "=r"(hp) : "f"(x1), "f"(x0));
    float h0 = __uint_as_float(hp << 16);
    float h1 = __uint_as_float(hp & 0xffff0000u);
    asm("cvt.rn.bf16x2.f32 %0, %1, %2;" : "=r"(lp) : "f"(x1 - h1), "f"(x0 - h0));
}
__device__ __forceinline__ void ldsm4(uint32_t& r0, uint32_t& r1, uint32_t& r2,
                                      uint32_t& r3, uint32_t addr) {
    asm volatile("ldmatrix.sync.aligned.m8n8.x4.shared.b16 {%0,%1,%2,%3}, [%4];"
                 : "=r"(r0), "=r"(r1), "=r"(r2), "=r"(r3) : "r"(addr));
}
__device__ __forceinline__ void mma16816(float* c, uint32_t a0, uint32_t a1,
                                         uint32_t a2, uint32_t a3,
                                         uint32_t b0, uint32_t b1) {
    asm volatile(
        "mma.sync.aligned.m16n8k16.row.col.f32.bf16.bf16.f32 "
        "{%0,%1,%2,%3}, {%4,%5,%6,%7}, {%8,%9}, {%0,%1,%2,%3};"
        : "+f"(c[0]), "+f"(c[1]), "+f"(c[2]), "+f"(c[3])
        : "r"(a0), "r"(a1), "r"(a2), "r"(a3), "r"(b0), "r"(b1));
}

// overflow-safe activations (err ~1e-6; proven rel_err 2.4e-7 in prior rounds)
__device__ __forceinline__ float fast_sig(float x) {
    return __fdividef(1.0f, 1.0f + __expf(-x));
}
__device__ __forceinline__ float fast_tanh(float x) {
    return 1.0f - __fdividef(2.0f, __expf(2.0f * x) + 1.0f);
}

__global__ __launch_bounds__(TILE_B)
void lstm_mma_kernel(const float* __restrict__ x,
                     const float* __restrict__ Wih,   // [64][64]
                     const float* __restrict__ Whh,   // [64][16]
                     const float* __restrict__ bih,
                     const float* __restrict__ bhh,
                     const float* __restrict__ fcw,   // [16]
                     const float* __restrict__ fcb,
                     float* __restrict__ out,
                     int batch)
{
    extern __shared__ __align__(16) char sm[];
    const uint32_t smb = s2u(sm);
    const int tid  = threadIdx.x;
    const int lane = tid & 31, warp = tid >> 5;
    const int g = lane >> 2, j = lane & 3;    // mma group / pair index

    // ---- prologue: Wih -> split-bf16 smem ----
    {
        int r = tid >> 1, cb = (tid & 1) * 32;
        const float4* wr = (const float4*)(Wih + r * INS + cb);
#pragma unroll
        for (int q = 0; q < 4; q++) {
            float4 qa = __ldg(&wr[2 * q]);
            float4 qb = __ldg(&wr[2 * q + 1]);
            uint32_t hh[4], ll[4];
            cvt2(hh[0], ll[0], qa.x, qa.y);
            cvt2(hh[1], ll[1], qa.z, qa.w);
            cvt2(hh[2], ll[2], qb.x, qb.y);
            cvt2(hh[3], ll[3], qb.z, qb.w);
            int off = r * XSTRIDE + cb * 2 + q * 16;
            *(uint4*)(sm + SM_WIH_HI + off) = make_uint4(hh[0], hh[1], hh[2], hh[3]);
            *(uint4*)(sm + SM_WIH_LO + off) = make_uint4(ll[0], ll[1], ll[2], ll[3]);
        }
    }
    for (int idx = tid; idx < 64 * HID; idx += TILE_B)
        ((float*)(sm + SM_WHH))[idx] = Whh[idx];
    if (tid < 64)  ((float*)(sm + SM_BIAS))[tid] = bih[tid] + bhh[tid];
    if (tid < HID) ((float*)(sm + SM_FCW))[tid]  = fcw[tid];
    if (tid == 0)  *(float*)(sm + SM_FCB)        = fcb[0];
    __syncthreads();

    const int row0  = blockIdx.x * TILE_B + warp * 32;  // warp's first row
    const int myrow = row0 + lane;                      // row this lane converts
    const int crow  = myrow < batch ? myrow : batch - 1;
    const float4* xrow = (const float4*)(x + (size_t)crow * SEQT * INS);

    // ldmatrix per-thread address bases
    const int mrow = lane & 7, msel = lane >> 3;
    const uint32_t a_base = smb + SM_X_HI +
        (warp * 32 + (msel & 1) * 8 + mrow) * XSTRIDE + (msel >> 1) * 16;
    const uint32_t b_base = smb + SM_WIH_HI +
        ((msel >> 1) * 8 + mrow) * XSTRIDE + (msel & 1) * 16;

    // x smem write pointers (this lane's row)
    char* xw_hi = sm + SM_X_HI + (warp * 32 + lane) * XSTRIDE;
    char* xw_lo = sm + SM_X_LO + (warp * 32 + lane) * XSTRIDE;

    // state: h/c [m-tile][row-half][unit 0..3]; units {2j,2j+1,8+2j,8+2j+1}
    float h[2][2][4], c[2][2][4];
#pragma unroll
    for (int mt = 0; mt < 2; mt++)
#pragma unroll
        for (int rh = 0; rh < 2; rh++)
#pragma unroll
            for (int u = 0; u < 4; u++) { h[mt][rh][u] = 0.f; c[mt][rh][u] = 0.f; }

#pragma unroll 1
    for (int t = 0; t < SEQT; t++) {
        // ---- 1. convert my x row to split-bf16 smem ----
        const float4* src = xrow + t * 16;
#pragma unroll
        for (int i8 = 0; i8 < 8; i8++) {
            float4 qa = __ldg(&src[2 * i8]);
            float4 qb = __ldg(&src[2 * i8 + 1]);
            uint32_t hh[4], ll[4];
            cvt2(hh[0], ll[0], qa.x, qa.y);
            cvt2(hh[1], ll[1], qa.z, qa.w);
            cvt2(hh[2], ll[2], qb.x, qb.y);
            cvt2(hh[3], ll[3], qb.z, qb.w);
            *(uint4*)(xw_hi + i8 * 16) = make_uint4(hh[0], hh[1], hh[2], hh[3]);
            *(uint4*)(xw_lo + i8 * 16) = make_uint4(ll[0], ll[1], ll[2], ll[3]);
        }
        __syncwarp();

        // ---- 2. acc init from bias ----
        float acc[2][8][4];
#pragma unroll
        for (int nt = 0; nt < 8; nt++) {
            float2 bv = *(const float2*)((const float*)(sm + SM_BIAS) + nt * 8 + 2 * j);
#pragma unroll
            for (int mt = 0; mt < 2; mt++) {
                acc[mt][nt][0] = bv.x; acc[mt][nt][1] = bv.y;
                acc[mt][nt][2] = bv.x; acc[mt][nt][3] = bv.y;
            }
        }

        // ---- 3. recurrence mma: gates += h @ Whh^T  (h frag built in-register) ----
        if (t > 0) {
            uint32_t ahi[2][4], alo[2][4];
#pragma unroll
            for (int mt = 0; mt < 2; mt++) {
                cvt2(ahi[mt][0], alo[mt][0], h[mt][0][0], h[mt][0][1]);
                cvt2(ahi[mt][1], alo[mt][1], h[mt][1][0], h[mt][1][1]);
                cvt2(ahi[mt][2], alo[mt][2], h[mt][0][2], h[mt][0][3]);
                cvt2(ahi[mt][3], alo[mt][3], h[mt][1][2], h[mt][1][3]);
            }
#pragma unroll
            for (int nt = 0; nt < 8; nt++) {
                const float* wrow = (const float*)(sm + SM_WHH) + (nt * 8 + g) * HID;
                float2 w0 = *(const float2*)(wrow + 2 * j);
                float2 w1 = *(const float2*)(wrow + 8 + 2 * j);
                uint32_t b0h, b0l, b1h, b1l;
                cvt2(b0h, b0l, w0.x, w0.y);
                cvt2(b1h, b1l, w1.x, w1.y);
#pragma unroll
                for (int mt = 0; mt < 2; mt++) {
                    mma16816(acc[mt][nt], ahi[mt][0], ahi[mt][1], ahi[mt][2], ahi[mt][3], b0h, b1h);
                    mma16816(acc[mt][nt], alo[mt][0], alo[mt][1], alo[mt][2], alo[mt][3], b0h, b1h);
                    mma16816(acc[mt][nt], ahi[mt][0], ahi[mt][1], ahi[mt][2], ahi[mt][3], b0l, b1l);
                }
            }
        }

        // ---- 4. x-GEMM: gates += x @ Wih^T, split-bf16 3 passes ----
#pragma unroll
        for (int ks = 0; ks < 4; ks++) {
            uint32_t Ah[2][4], Al[2][4];
#pragma unroll
            for (int mt = 0; mt < 2; mt++) {
                uint32_t aa = a_base + mt * (16 * XSTRIDE) + ks * 32;
                ldsm4(Ah[mt][0], Ah[mt][1], Ah[mt][2], Ah[mt][3], aa);
                ldsm4(Al[mt][0], Al[mt][1], Al[mt][2], Al[mt][3], aa + 18432);
            }
#pragma unroll
            for (int p = 0; p < 4; p++) {
                uint32_t bb = b_base + p * (16 * XSTRIDE) + ks * 32;
                uint32_t Bh[4], Bl[4];
                ldsm4(Bh[0], Bh[1], Bh[2], Bh[3], bb);
                ldsm4(Bl[0], Bl[1], Bl[2], Bl[3], bb + 9216);
#pragma unroll
                for (int mt = 0; mt < 2; mt++) {
                    mma16816(acc[mt][2 * p],     Ah[mt][0], Ah[mt][1], Ah[mt][2], Ah[mt][3], Bh[0], Bh[1]);
                    mma16816(acc[mt][2 * p + 1], Ah[mt][0], Ah[mt][1], Ah[mt][2], Ah[mt][3], Bh[2], Bh[3]);
                    mma16816(acc[mt][2 * p],     Al[mt][0], Al[mt][1], Al[mt][2], Al[mt][3], Bh[0], Bh[1]);
                    mma16816(acc[mt][2 * p + 1], Al[mt][0], Al[mt][1], Al[mt][2], Al[mt][3], Bh[2], Bh[3]);
                    mma16816(acc[mt][2 * p],     Ah[mt][0], Ah[mt][1], Ah[mt][2], Ah[mt][3], Bl[0], Bl[1]);
                    mma16816(acc[mt][2 * p + 1], Ah[mt][0], Ah[mt][1], Ah[mt][2], Ah[mt][3], Bl[2], Bl[3]);
                }
            }
        }

        // ---- 5. activations + state update (thread-local) ----
        // gate q lives in tiles {2q, 2q+1}; unit u: tile +(u>>1), reg (u&1)+2*rh
#pragma unroll
        for (int mt = 0; mt < 2; mt++)
#pragma unroll
            for (int rh = 0; rh < 2; rh++)
#pragma unroll
                for (int u = 0; u < 4; u++) {
                    const int tb = u >> 1, rg = (u & 1) + 2 * rh;
                    float gi = acc[mt][0 + tb][rg];
                    float gf = acc[mt][2 + tb][rg];
                    float gg = acc[mt][4 + tb][rg];
                    float go = acc[mt][6 + tb][rg];
                    float ig = fast_sig(gi), fg = fast_sig(gf);
                    float g2 = fast_tanh(gg), og = fast_sig(go);
                    float cn = fg * c[mt][rh][u] + ig * g2;
                    c[mt][rh][u] = cn;
                    h[mt][rh][u] = og * fast_tanh(cn);
                }
    }

    // ---- fc head: rows of a group reduce over its 4 lanes ----
    {
        const float* fwp = (const float*)(sm + SM_FCW);
        float2 fw0 = *(const float2*)(fwp + 2 * j);
        float2 fw1 = *(const float2*)(fwp + 8 + 2 * j);
        float fb = *(const float*)(sm + SM_FCB);
#pragma unroll
        for (int mt = 0; mt < 2; mt++)
#pragma unroll
            for (int rh = 0; rh < 2; rh++) {
                float p = h[mt][rh][0] * fw0.x + h[mt][rh][1] * fw0.y +
                          h[mt][rh][2] * fw1.x + h[mt][rh][3] * fw1.y;
                p += __shfl_xor_sync(0xffffffffu, p, 1);
                p += __shfl_xor_sync(0xffffffffu, p, 2);
                if (j == 0) {
                    int row = row0 + mt * 16 + rh * 8 + g;
                    if (row < batch) out[row] = p + fb;
                }
            }
    }
}

extern "C" void kernel_launch(void* const* d_in, const int* in_sizes, int n_in,
                              void* d_out, int out_size)
{
    const float* x   = (const float*)d_in[0];
    const float* Wih = (const float*)d_in[1];
    const float* Whh = (const float*)d_in[2];
    const float* bih = (const float*)d_in[3];
    const float* bhh = (const float*)d_in[4];
    const float* fcw = (const float*)d_in[5];
    const float* fcb = (const float*)d_in[6];
    float* out = (float*)d_out;

    int batch = in_sizes[0] / (SEQT * INS);

    cudaFuncSetAttribute(lstm_mma_kernel,
                         cudaFuncAttributeMaxDynamicSharedMemorySize, SM_TOTAL);

    int blocks = (batch + TILE_B - 1) / TILE_B;
    lstm_mma_kernel<<<blocks, TILE_B, SM_TOTAL>>>(x, Wih, Whh, bih, bhh,
                                                  fcw, fcb, out, batch);
}

// round 11
// speedup vs baseline: 4.1304x; 1.2333x over previous
#include <cuda_runtime.h>
#include <cstdint>

#define HID   16
#define INS   64
#define SEQT  12
#define RW    16           // rows per warp
#define NWARP 4
#define TILE_B (RW * NWARP)
#define XSTR  144          // padded stage row stride (bytes), conflict-free
#define WSTAGE (2 * RW * XSTR)   // per-warp stage (hi+lo planes) = 4608

__device__ __forceinline__ uint32_t s2u(const void* p) {
    uint32_t a;
    asm("{ .reg .u64 t; cvta.to.shared.u64 t, %1; cvt.u32.u64 %0, t; }"
        : "=r"(a) : "l"(p));
    return a;
}
// split-fp16: (x0,x1) -> hi pack {lo16=f16(x0), hi16=f16(x1)} + residual pack
__device__ __forceinline__ void packsplit(uint32_t& hp, uint32_t& lp,
                                          float x0, float x1) {
    asm("cvt.rn.f16x2.f32 %0, %1, %2;" : "=r"(hp) : "f"(x1), "f"(x0));
    float f0, f1;
    asm("{.reg .f16 l, h; mov.b32 {l, h}, %2; cvt.f32.f16 %0, l; cvt.f32.f16 %1, h;}"
        : "=f"(f0), "=f"(f1) : "r"(hp));
    asm("cvt.rn.f16x2.f32 %0, %1, %2;" : "=r"(lp) : "f"(x1 - f1), "f"(x0 - f0));
}
// hi-only pack (for weights; residual intentionally dropped -> 2-pass scheme)
__device__ __forceinline__ uint32_t packh(float x0, float x1) {
    uint32_t u;
    asm("cvt.rn.f16x2.f32 %0, %1, %2;" : "=r"(u) : "f"(x1), "f"(x0));
    return u;
}
__device__ __forceinline__ void ldsm4(uint32_t& r0, uint32_t& r1, uint32_t& r2,
                                      uint32_t& r3, uint32_t addr) {
    asm volatile("ldmatrix.sync.aligned.m8n8.x4.shared.b16 {%0,%1,%2,%3}, [%4];"
                 : "=r"(r0), "=r"(r1), "=r"(r2), "=r"(r3) : "r"(addr));
}
__device__ __forceinline__ void mma16816(float* c, uint32_t a0, uint32_t a1,
                                         uint32_t a2, uint32_t a3,
                                         uint32_t b0, uint32_t b1) {
    asm volatile(
        "mma.sync.aligned.m16n8k16.row.col.f32.f16.f16.f32 "
        "{%0,%1,%2,%3}, {%4,%5,%6,%7}, {%8,%9}, {%0,%1,%2,%3};"
        : "+f"(c[0]), "+f"(c[1]), "+f"(c[2]), "+f"(c[3])
        : "r"(a0), "r"(a1), "r"(a2), "r"(a3), "r"(b0), "r"(b1));
}
// overflow-safe activations
__device__ __forceinline__ float fast_sig(float x) {
    return __fdividef(1.0f, 1.0f + __expf(-x));
}
__device__ __forceinline__ float fast_tanh(float x) {
    return 1.0f - __fdividef(2.0f, __expf(2.0f * x) + 1.0f);
}

__global__ __launch_bounds__(128)
void lstm_mma2_kernel(const float* __restrict__ x,
                      const float* __restrict__ Wih,   // [64][64]
                      const float* __restrict__ Whh,   // [64][16]
                      const float* __restrict__ bih,
                      const float* __restrict__ bhh,
                      const float* __restrict__ fcw,   // [16]
                      const float* __restrict__ fcb,
                      float* __restrict__ out,
                      int batch)
{
    __shared__ __align__(16) char  s_x[NWARP * WSTAGE];  // per-warp hi+lo planes
    __shared__ __align__(16) float s_bias[64];
    __shared__ __align__(16) float s_fcw[HID];
    __shared__ float s_fcb;

    const int tid  = threadIdx.x;
    const int lane = tid & 31, warp = tid >> 5;
    const int g = lane >> 2, j = lane & 3;

    if (tid < 64)  s_bias[tid] = bih[tid] + bhh[tid];
    if (tid < HID) s_fcw[tid]  = fcw[tid];
    if (tid == 0)  s_fcb       = fcb[0];
    __syncthreads();

    // ---- hoist W fragments (hi plane only) into registers, once ----
    uint32_t Bx[4][8][2];          // x-GEMM B frags: [ks][ntile][b0,b1]
#pragma unroll
    for (int ks = 0; ks < 4; ks++)
#pragma unroll
        for (int nt = 0; nt < 8; nt++) {
            const float2* p =
                (const float2*)(Wih + (8 * nt + g) * INS + 16 * ks + 2 * j);
            float2 w0 = __ldg(p);        // k = 2j, 2j+1
            float2 w1 = __ldg(p + 4);    // k = 8+2j, 8+2j+1
            Bx[ks][nt][0] = packh(w0.x, w0.y);
            Bx[ks][nt][1] = packh(w1.x, w1.y);
        }
    uint32_t Bhh[8][2];            // recurrence B frags (k16 = HID)
#pragma unroll
    for (int nt = 0; nt < 8; nt++) {
        const float2* p = (const float2*)(Whh + (8 * nt + g) * HID + 2 * j);
        float2 w0 = __ldg(p);
        float2 w1 = __ldg(p + 4);
        Bhh[nt][0] = packh(w0.x, w0.y);
        Bhh[nt][1] = packh(w1.x, w1.y);
    }

    const int rowbase = blockIdx.x * TILE_B + warp * RW;

    // staging addresses
    const int mrow = lane & 7, msel = lane >> 3;
    const uint32_t smb = s2u(s_x);
    const uint32_t a_hi = smb + warp * WSTAGE +
        ((msel & 1) * 8 + mrow) * XSTR + (msel >> 1) * 16;
    const uint32_t a_lo = a_hi + RW * XSTR;

    // conversion: lane handles row (lane>>1), column half (lane&1)
    const int crow = rowbase + (lane >> 1) < batch ? rowbase + (lane >> 1)
                                                   : batch - 1;
    const float4* xsrc =
        (const float4*)(x + (size_t)crow * SEQT * INS) + (lane & 1) * 8;
    char* hs = s_x + warp * WSTAGE + (lane >> 1) * XSTR + (lane & 1) * 64;
    char* ls = hs + RW * XSTR;

    // state: h/c [row-half rh][unit uu]; units {2j,2j+1,8+2j,8+2j+1}
    float h[2][4], c[2][4];
#pragma unroll
    for (int rh = 0; rh < 2; rh++)
#pragma unroll
        for (int u = 0; u < 4; u++) { h[rh][u] = 0.f; c[rh][u] = 0.f; }

#pragma unroll 1
    for (int t = 0; t < SEQT; t++) {
        // ---- 1. stage x (split-fp16, hi + lo planes) ----
        const float4* src = xsrc + t * 16;
#pragma unroll
        for (int i = 0; i < 4; i++) {
            float4 a = __ldg(&src[2 * i]);
            float4 b = __ldg(&src[2 * i + 1]);
            uint4 H, L;
            packsplit(H.x, L.x, a.x, a.y);
            packsplit(H.y, L.y, a.z, a.w);
            packsplit(H.z, L.z, b.x, b.y);
            packsplit(H.w, L.w, b.z, b.w);
            *(uint4*)(hs + i * 16) = H;
            *(uint4*)(ls + i * 16) = L;
        }
        __syncwarp();

        // ---- 2. acc init from bias ----
        float acc[8][4];
#pragma unroll
        for (int nt = 0; nt < 8; nt++) {
            float2 bv = *(const float2*)(s_bias + 8 * nt + 2 * j);
            acc[nt][0] = bv.x; acc[nt][1] = bv.y;
            acc[nt][2] = bv.x; acc[nt][3] = bv.y;
        }

        // ---- 3. recurrence: gates += h @ Whh^T (2-pass split, B in regs) ----
        if (t > 0) {
            uint32_t ah[4], al[4];
            packsplit(ah[0], al[0], h[0][0], h[0][1]);
            packsplit(ah[1], al[1], h[1][0], h[1][1]);
            packsplit(ah[2], al[2], h[0][2], h[0][3]);
            packsplit(ah[3], al[3], h[1][2], h[1][3]);
#pragma unroll
            for (int nt = 0; nt < 8; nt++) {
                mma16816(acc[nt], ah[0], ah[1], ah[2], ah[3],
                         Bhh[nt][0], Bhh[nt][1]);
                mma16816(acc[nt], al[0], al[1], al[2], al[3],
                         Bhh[nt][0], Bhh[nt][1]);
            }
        }

        // ---- 4. x-GEMM: gates += x @ Wih^T (2-pass split, B in regs) ----
#pragma unroll
        for (int ks = 0; ks < 4; ks++) {
            uint32_t Ah[4], Al[4];
            ldsm4(Ah[0], Ah[1], Ah[2], Ah[3], a_hi + ks * 32);
            ldsm4(Al[0], Al[1], Al[2], Al[3], a_lo + ks * 32);
#pragma unroll
            for (int nt = 0; nt < 8; nt++) {
                mma16816(acc[nt], Ah[0], Ah[1], Ah[2], Ah[3],
                         Bx[ks][nt][0], Bx[ks][nt][1]);
                mma16816(acc[nt], Al[0], Al[1], Al[2], Al[3],
                         Bx[ks][nt][0], Bx[ks][nt][1]);
            }
        }

        // ---- 5. activations + state update (thread-local) ----
        // gate q of unit uu: nt = 2q + (uu>>1), reg = (uu&1) + 2*rh
#pragma unroll
        for (int rh = 0; rh < 2; rh++)
#pragma unroll
            for (int uu = 0; uu < 4; uu++) {
                const int nth = uu >> 1, rg = (uu & 1) + 2 * rh;
                float gi = acc[0 + nth][rg];
                float gf = acc[2 + nth][rg];
                float gg = acc[4 + nth][rg];
                float go = acc[6 + nth][rg];
                float ig = fast_sig(gi), fg = fast_sig(gf);
                float g2 = fast_tanh(gg), og = fast_sig(go);
                float cn = fg * c[rh][uu] + ig * g2;
                c[rh][uu] = cn;
                h[rh][uu] = og * fast_tanh(cn);
            }
    }

    // ---- fc head: reduce over the 4 j-lanes of each row ----
    {
        float2 f0 = *(const float2*)(s_fcw + 2 * j);
        float2 f1 = *(const float2*)(s_fcw + 8 + 2 * j);
        float fb = s_fcb;
#pragma unroll
        for (int rh = 0; rh < 2; rh++) {
            float p = h[rh][0] * f0.x + h[rh][1] * f0.y +
                      h[rh][2] * f1.x + h[rh][3] * f1.y;
            p += __shfl_xor_sync(0xffffffffu, p, 1);
            p += __shfl_xor_sync(0xffffffffu, p, 2);
            if (j == 0) {
                int row = rowbase + rh * 8 + g;
                if (row < batch) out[row] = p + fb;
            }
        }
    }
}

extern "C" void kernel_launch(void* const* d_in, const int* in_sizes, int n_in,
                              void* d_out, int out_size)
{
    const float* x   = (const float*)d_in[0];
    const float* Wih = (const float*)d_in[1];
    const float* Whh = (const float*)d_in[2];
    const float* bih = (const float*)d_in[3];
    const float* bhh = (const float*)d_in[4];
    const float* fcw = (const float*)d_in[5];
    const float* fcb = (const float*)d_in[6];
    float* out = (float*)d_out;

    int batch = in_sizes[0] / (SEQT * INS);
    int blocks = (batch + TILE_B - 1) / TILE_B;
    lstm_mma2_kernel<<<blocks, 128>>>(x, Wih, Whh, bih, bhh, fcw, fcb,
                                      out, batch);
}

// round 12
// speedup vs baseline: 4.7175x; 1.1421x over previous
#include <cuda_runtime.h>
#include <cstdint>

#define HID   16
#define INS   64
#define SEQT  12
#define RW    16           // rows per warp
#define NWARP 4
#define TILE_B (RW * NWARP)
#define XSTR  144          // padded stage row stride (bytes), conflict-free
#define WSTAGE (2 * RW * XSTR)   // per-warp stage (hi+lo planes) = 4608

__device__ __forceinline__ uint32_t s2u(const void* p) {
    uint32_t a;
    asm("{ .reg .u64 t; cvta.to.shared.u64 t, %1; cvt.u32.u64 %0, t; }"
        : "=r"(a) : "l"(p));
    return a;
}
// split-fp16: (x0,x1) -> hi pack {lo16=f16(x0), hi16=f16(x1)} + residual pack
__device__ __forceinline__ void packsplit(uint32_t& hp, uint32_t& lp,
                                          float x0, float x1) {
    asm("cvt.rn.f16x2.f32 %0, %1, %2;" : "=r"(hp) : "f"(x1), "f"(x0));
    float f0, f1;
    asm("{.reg .f16 l, h; mov.b32 {l, h}, %2; cvt.f32.f16 %0, l; cvt.f32.f16 %1, h;}"
        : "=f"(f0), "=f"(f1) : "r"(hp));
    asm("cvt.rn.f16x2.f32 %0, %1, %2;" : "=r"(lp) : "f"(x1 - f1), "f"(x0 - f0));
}
// hi-only pack (for weights; residual intentionally dropped -> 2-pass scheme)
__device__ __forceinline__ uint32_t packh(float x0, float x1) {
    uint32_t u;
    asm("cvt.rn.f16x2.f32 %0, %1, %2;" : "=r"(u) : "f"(x1), "f"(x0));
    return u;
}
__device__ __forceinline__ void ldsm4(uint32_t& r0, uint32_t& r1, uint32_t& r2,
                                      uint32_t& r3, uint32_t addr) {
    asm volatile("ldmatrix.sync.aligned.m8n8.x4.shared.b16 {%0,%1,%2,%3}, [%4];"
                 : "=r"(r0), "=r"(r1), "=r"(r2), "=r"(r3) : "r"(addr));
}
__device__ __forceinline__ void mma16816(float* c, uint32_t a0, uint32_t a1,
                                         uint32_t a2, uint32_t a3,
                                         uint32_t b0, uint32_t b1) {
    asm volatile(
        "mma.sync.aligned.m16n8k16.row.col.f32.f16.f16.f32 "
        "{%0,%1,%2,%3}, {%4,%5,%6,%7}, {%8,%9}, {%0,%1,%2,%3};"
        : "+f"(c[0]), "+f"(c[1]), "+f"(c[2]), "+f"(c[3])
        : "r"(a0), "r"(a1), "r"(a2), "r"(a3), "r"(b0), "r"(b1));
}
// overflow-safe activations
__device__ __forceinline__ float fast_sig(float x) {
    return __fdividef(1.0f, 1.0f + __expf(-x));
}
__device__ __forceinline__ float fast_tanh(float x) {
    return 1.0f - __fdividef(2.0f, __expf(2.0f * x) + 1.0f);
}

__global__ __launch_bounds__(128)
void lstm_mma3_kernel(const float* __restrict__ x,
                      const float* __restrict__ Wih,   // [64][64]
                      const float* __restrict__ Whh,   // [64][16]
                      const float* __restrict__ bih,
                      const float* __restrict__ bhh,
                      const float* __restrict__ fcw,   // [16]
                      const float* __restrict__ fcb,
                      float* __restrict__ out,
                      int batch)
{
    __shared__ __align__(16) char  s_x[NWARP * WSTAGE];  // per-warp hi+lo planes
    __shared__ __align__(16) float s_bias[64];
    __shared__ __align__(16) float s_fcw[HID];
    __shared__ float s_fcb;

    const int tid  = threadIdx.x;
    const int lane = tid & 31, warp = tid >> 5;
    const int g = lane >> 2, j = lane & 3;

    if (tid < 64)  s_bias[tid] = bih[tid] + bhh[tid];
    if (tid < HID) s_fcw[tid]  = fcw[tid];
    if (tid == 0)  s_fcb       = fcb[0];
    __syncthreads();

    // ---- hoist W fragments (hi plane only) into registers, once ----
    uint32_t Bx[4][8][2];          // x-GEMM B frags: [ks][ntile][b0,b1]
#pragma unroll
    for (int ks = 0; ks < 4; ks++)
#pragma unroll
        for (int nt = 0; nt < 8; nt++) {
            const float2* p =
                (const float2*)(Wih + (8 * nt + g) * INS + 16 * ks + 2 * j);
            float2 w0 = __ldg(p);        // k = 2j, 2j+1
            float2 w1 = __ldg(p + 4);    // k = 8+2j, 8+2j+1
            Bx[ks][nt][0] = packh(w0.x, w0.y);
            Bx[ks][nt][1] = packh(w1.x, w1.y);
        }
    uint32_t Bhh[8][2];            // recurrence B frags (k16 = HID)
#pragma unroll
    for (int nt = 0; nt < 8; nt++) {
        const float2* p = (const float2*)(Whh + (8 * nt + g) * HID + 2 * j);
        float2 w0 = __ldg(p);
        float2 w1 = __ldg(p + 4);
        Bhh[nt][0] = packh(w0.x, w0.y);
        Bhh[nt][1] = packh(w1.x, w1.y);
    }

    // per-warp row base, clamped so all 16 rows are in range (duplicate work
    // across CTAs for the tail is deterministic-identical, writes stay correct)
    int rowbase = blockIdx.x * TILE_B + warp * RW;
    if (rowbase + RW > batch) rowbase = batch >= RW ? batch - RW : 0;

    // ---- coalesced x staging: lanes 0-15 = row 2i, lanes 16-31 = row 2i+1 ----
    const int half = lane >> 4, q = lane & 15;
    const float* xb = x + (size_t)(rowbase + half) * (SEQT * INS) + q * 4;
    char* hs = s_x + warp * WSTAGE + half * XSTR + q * 8;
    char* ls = hs + RW * XSTR;

    // ldmatrix fragment addresses (row g / g+8, k-halves)
    const int mrow = lane & 7, msel = lane >> 3;
    const uint32_t smb = s2u(s_x);
    const uint32_t a_hi = smb + warp * WSTAGE +
        ((msel & 1) * 8 + mrow) * XSTR + (msel >> 1) * 16;
    const uint32_t a_lo = a_hi + RW * XSTR;

    // state: h/c [row-half rh][unit uu]; units {2j,2j+1,8+2j,8+2j+1}
    float h[2][4], c[2][4];
#pragma unroll
    for (int rh = 0; rh < 2; rh++)
#pragma unroll
        for (int u = 0; u < 4; u++) { h[rh][u] = 0.f; c[rh][u] = 0.f; }

#pragma unroll 1
    for (int t = 0; t < SEQT; t++) {
        // ---- 1. coalesced load + split-fp16 convert + stage ----
        const float* xt = xb + t * INS;
#pragma unroll
        for (int i = 0; i < 8; i++) {
            float4 f = __ldg((const float4*)(xt + i * (2 * SEQT * INS)));
            uint2 H, L;
            packsplit(H.x, L.x, f.x, f.y);
            packsplit(H.y, L.y, f.z, f.w);
            *(uint2*)(hs + i * (2 * XSTR)) = H;
            *(uint2*)(ls + i * (2 * XSTR)) = L;
        }

        // ---- 2. acc init from bias ----
        float acc[8][4];
#pragma unroll
        for (int nt = 0; nt < 8; nt++) {
            float2 bv = *(const float2*)(s_bias + 8 * nt + 2 * j);
            acc[nt][0] = bv.x; acc[nt][1] = bv.y;
            acc[nt][2] = bv.x; acc[nt][3] = bv.y;
        }

        // ---- 3. recurrence: gates += h @ Whh^T (2-pass split, B in regs) ----
        //      (also covers the STS->ldmatrix distance)
        if (t > 0) {
            uint32_t ah[4], al[4];
            packsplit(ah[0], al[0], h[0][0], h[0][1]);
            packsplit(ah[1], al[1], h[1][0], h[1][1]);
            packsplit(ah[2], al[2], h[0][2], h[0][3]);
            packsplit(ah[3], al[3], h[1][2], h[1][3]);
#pragma unroll
            for (int nt = 0; nt < 8; nt++) {
                mma16816(acc[nt], ah[0], ah[1], ah[2], ah[3],
                         Bhh[nt][0], Bhh[nt][1]);
                mma16816(acc[nt], al[0], al[1], al[2], al[3],
                         Bhh[nt][0], Bhh[nt][1]);
            }
        }
        __syncwarp();

        // ---- 4. x-GEMM: gates += x @ Wih^T (2-pass split, B in regs) ----
#pragma unroll
        for (int ks = 0; ks < 4; ks++) {
            uint32_t Ah[4], Al[4];
            ldsm4(Ah[0], Ah[1], Ah[2], Ah[3], a_hi + ks * 32);
            ldsm4(Al[0], Al[1], Al[2], Al[3], a_lo + ks * 32);
#pragma unroll
            for (int nt = 0; nt < 8; nt++) {
                mma16816(acc[nt], Ah[0], Ah[1], Ah[2], Ah[3],
                         Bx[ks][nt][0], Bx[ks][nt][1]);
                mma16816(acc[nt], Al[0], Al[1], Al[2], Al[3],
                         Bx[ks][nt][0], Bx[ks][nt][1]);
            }
        }

        // ---- 5. activations + state update (thread-local) ----
        // gate qg of unit uu: nt = 2*qg + (uu>>1), reg = (uu&1) + 2*rh
#pragma unroll
        for (int rh = 0; rh < 2; rh++)
#pragma unroll
            for (int uu = 0; uu < 4; uu++) {
                const int nth = uu >> 1, rg = (uu & 1) + 2 * rh;
                float gi = acc[0 + nth][rg];
                float gf = acc[2 + nth][rg];
                float gg = acc[4 + nth][rg];
                float go = acc[6 + nth][rg];
                float ig = fast_sig(gi), fg = fast_sig(gf);
                float g2 = fast_tanh(gg), og = fast_sig(go);
                float cn = fg * c[rh][uu] + ig * g2;
                c[rh][uu] = cn;
                h[rh][uu] = og * fast_tanh(cn);
            }
        __syncwarp();   // all lanes done with ldsm before next step's STS
    }

    // ---- fc head: reduce over the 4 j-lanes of each row ----
    {
        float2 f0 = *(const float2*)(s_fcw + 2 * j);
        float2 f1 = *(const float2*)(s_fcw + 8 + 2 * j);
        float fb = s_fcb;
#pragma unroll
        for (int rh = 0; rh < 2; rh++) {
            float p = h[rh][0] * f0.x + h[rh][1] * f0.y +
                      h[rh][2] * f1.x + h[rh][3] * f1.y;
            p += __shfl_xor_sync(0xffffffffu, p, 1);
            p += __shfl_xor_sync(0xffffffffu, p, 2);
            if (j == 0) {
                int row = rowbase + rh * 8 + g;
                if (row < batch) out[row] = p + fb;
            }
        }
    }
}

extern "C" void kernel_launch(void* const* d_in, const int* in_sizes, int n_in,
                              void* d_out, int out_size)
{
    const float* x   = (const float*)d_in[0];
    const float* Wih = (const float*)d_in[1];
    const float* Whh = (const float*)d_in[2];
    const float* bih = (const float*)d_in[3];
    const float* bhh = (const float*)d_in[4];
    const float* fcw = (const float*)d_in[5];
    const float* fcb = (const float*)d_in[6];
    float* out = (float*)d_out;

    int batch = in_sizes[0] / (SEQT * INS);
    int blocks = (batch + TILE_B - 1) / TILE_B;
    lstm_mma3_kernel<<<blocks, 128>>>(x, Wih, Whh, bih, bhh, fcw, fcb,
                                      out, batch);
}

// round 13
// speedup vs baseline: 5.4147x; 1.1478x over previous
#include <cuda_runtime.h>
#include <cstdint>

#define HID   16
#define INS   64
#define SEQT  12
#define RW    16           // rows per warp
#define NWARP 4
#define TILE_B (RW * NWARP)
#define XSTR  144          // padded stage row stride (bytes), conflict-free
#define WSTAGE (2 * RW * XSTR)   // per-warp stage (hi+lo planes) = 4608

__device__ __forceinline__ uint32_t s2u(const void* p) {
    uint32_t a;
    asm("{ .reg .u64 t; cvta.to.shared.u64 t, %1; cvt.u32.u64 %0, t; }"
        : "=r"(a) : "l"(p));
    return a;
}
// split-fp16: (x0,x1) -> hi pack {lo16=f16(x0), hi16=f16(x1)} + residual pack
__device__ __forceinline__ void packsplit(uint32_t& hp, uint32_t& lp,
                                          float x0, float x1) {
    asm("cvt.rn.f16x2.f32 %0, %1, %2;" : "=r"(hp) : "f"(x1), "f"(x0));
    float f0, f1;
    asm("{.reg .f16 l, h; mov.b32 {l, h}, %2; cvt.f32.f16 %0, l; cvt.f32.f16 %1, h;}"
        : "=f"(f0), "=f"(f1) : "r"(hp));
    asm("cvt.rn.f16x2.f32 %0, %1, %2;" : "=r"(lp) : "f"(x1 - f1), "f"(x0 - f0));
}
// hi-only pack (for weights; residual intentionally dropped -> 2-pass scheme)
__device__ __forceinline__ uint32_t packh(float x0, float x1) {
    uint32_t u;
    asm("cvt.rn.f16x2.f32 %0, %1, %2;" : "=r"(u) : "f"(x1), "f"(x0));
    return u;
}
__device__ __forceinline__ void ldsm4(uint32_t& r0, uint32_t& r1, uint32_t& r2,
                                      uint32_t& r3, uint32_t addr) {
    asm volatile("ldmatrix.sync.aligned.m8n8.x4.shared.b16 {%0,%1,%2,%3}, [%4];"
                 : "=r"(r0), "=r"(r1), "=r"(r2), "=r"(r3) : "r"(addr));
}
__device__ __forceinline__ void mma16816(float* c, uint32_t a0, uint32_t a1,
                                         uint32_t a2, uint32_t a3,
                                         uint32_t b0, uint32_t b1) {
    asm volatile(
        "mma.sync.aligned.m16n8k16.row.col.f32.f16.f16.f32 "
        "{%0,%1,%2,%3}, {%4,%5,%6,%7}, {%8,%9}, {%0,%1,%2,%3};"
        : "+f"(c[0]), "+f"(c[1]), "+f"(c[2]), "+f"(c[3])
        : "r"(a0), "r"(a1), "r"(a2), "r"(a3), "r"(b0), "r"(b1));
}
// overflow-safe activations
__device__ __forceinline__ float fast_sig(float x) {
    return __fdividef(1.0f, 1.0f + __expf(-x));
}
__device__ __forceinline__ float fast_tanh(float x) {
    return 1.0f - __fdividef(2.0f, __expf(2.0f * x) + 1.0f);
}

__global__ __launch_bounds__(128, 4)
void lstm_mma4_kernel(const float* __restrict__ x,
                      const float* __restrict__ Wih,   // [64][64]
                      const float* __restrict__ Whh,   // [64][16]
                      const float* __restrict__ bih,
                      const float* __restrict__ bhh,
                      const float* __restrict__ fcw,   // [16]
                      const float* __restrict__ fcb,
                      float* __restrict__ out,
                      int batch)
{
    __shared__ __align__(16) char  s_x[NWARP * WSTAGE];   // per-warp hi+lo planes
    __shared__ __align__(16) uint2 s_bx[4 * 8 * 32];      // Wih frags/lane: 8KB
    __shared__ __align__(16) float s_bias[64];
    __shared__ __align__(16) float s_fcw[HID];
    __shared__ float s_fcb;

    const int tid  = threadIdx.x;
    const int lane = tid & 31, warp = tid >> 5;
    const int g = lane >> 2, j = lane & 3;

    if (tid < 64)  s_bias[tid] = bih[tid] + bhh[tid];
    if (tid < HID) s_fcw[tid]  = fcw[tid];
    if (tid == 0)  s_fcb       = fcb[0];

    // ---- pre-pack Wih B-fragments (hi plane) into smem; lane-indexed,
    //      identical for all warps, so warp 0 fills once ----
    if (warp == 0) {
#pragma unroll
        for (int ks = 0; ks < 4; ks++)
#pragma unroll
            for (int nt = 0; nt < 8; nt++) {
                const float2* p =
                    (const float2*)(Wih + (8 * nt + g) * INS + 16 * ks + 2 * j);
                float2 w0 = __ldg(p);        // k = 2j, 2j+1
                float2 w1 = __ldg(p + 4);    // k = 8+2j, 8+2j+1
                s_bx[(ks * 8 + nt) * 32 + lane] =
                    make_uint2(packh(w0.x, w0.y), packh(w1.x, w1.y));
            }
    }
    // recurrence B frags stay in registers (16)
    uint32_t Bhh[8][2];
#pragma unroll
    for (int nt = 0; nt < 8; nt++) {
        const float2* p = (const float2*)(Whh + (8 * nt + g) * HID + 2 * j);
        float2 w0 = __ldg(p);
        float2 w1 = __ldg(p + 4);
        Bhh[nt][0] = packh(w0.x, w0.y);
        Bhh[nt][1] = packh(w1.x, w1.y);
    }
    __syncthreads();

    int rowbase = blockIdx.x * TILE_B + warp * RW;
    if (rowbase + RW > batch) rowbase = batch >= RW ? batch - RW : 0;

    // ---- coalesced x staging: lanes 0-15 = even rows, 16-31 = odd rows ----
    const int half = lane >> 4, q = lane & 15;
    const float* xb = x + (size_t)(rowbase + half) * (SEQT * INS) + q * 4;
    char* hs = s_x + warp * WSTAGE + half * XSTR + q * 8;
    char* ls = hs + RW * XSTR;

    // ldmatrix fragment addresses
    const int mrow = lane & 7, msel = lane >> 3;
    const uint32_t smb = s2u(s_x);
    const uint32_t a_hi = smb + warp * WSTAGE +
        ((msel & 1) * 8 + mrow) * XSTR + (msel >> 1) * 16;
    const uint32_t a_lo = a_hi + RW * XSTR;
    const uint2* bxl = s_bx + lane;

    // state: h/c [row-half rh][unit uu]; units {2j,2j+1,8+2j,8+2j+1}
    float h[2][4], c[2][4];
#pragma unroll
    for (int rh = 0; rh < 2; rh++)
#pragma unroll
        for (int u = 0; u < 4; u++) { h[rh][u] = 0.f; c[rh][u] = 0.f; }

#pragma unroll 1
    for (int t = 0; t < SEQT; t++) {
        // ---- 1. coalesced load + split-fp16 convert + stage ----
        const float* xt = xb + t * INS;
#pragma unroll
        for (int i = 0; i < 8; i++) {
            float4 f = __ldg((const float4*)(xt + i * (2 * SEQT * INS)));
            uint2 H, L;
            packsplit(H.x, L.x, f.x, f.y);
            packsplit(H.y, L.y, f.z, f.w);
            *(uint2*)(hs + i * (2 * XSTR)) = H;
            *(uint2*)(ls + i * (2 * XSTR)) = L;
        }

        // ---- 2. acc init from bias ----
        float acc[8][4];
#pragma unroll
        for (int nt = 0; nt < 8; nt++) {
            float2 bv = *(const float2*)(s_bias + 8 * nt + 2 * j);
            acc[nt][0] = bv.x; acc[nt][1] = bv.y;
            acc[nt][2] = bv.x; acc[nt][3] = bv.y;
        }

        // ---- 3. recurrence: gates += h @ Whh^T (2-pass split, B in regs) ----
        //      (also covers the STS->ldmatrix distance)
        if (t > 0) {
            uint32_t ah[4], al[4];
            packsplit(ah[0], al[0], h[0][0], h[0][1]);
            packsplit(ah[1], al[1], h[1][0], h[1][1]);
            packsplit(ah[2], al[2], h[0][2], h[0][3]);
            packsplit(ah[3], al[3], h[1][2], h[1][3]);
#pragma unroll
            for (int nt = 0; nt < 8; nt++) {
                mma16816(acc[nt], ah[0], ah[1], ah[2], ah[3],
                         Bhh[nt][0], Bhh[nt][1]);
                mma16816(acc[nt], al[0], al[1], al[2], al[3],
                         Bhh[nt][0], Bhh[nt][1]);
            }
        }
        __syncwarp();

        // ---- 4. x-GEMM: gates += x @ Wih^T (2-pass, B frags from smem) ----
#pragma unroll
        for (int ks = 0; ks < 4; ks++) {
            uint32_t Ah[4], Al[4];
            ldsm4(Ah[0], Ah[1], Ah[2], Ah[3], a_hi + ks * 32);
            ldsm4(Al[0], Al[1], Al[2], Al[3], a_lo + ks * 32);
#pragma unroll
            for (int nt = 0; nt < 8; nt++) {
                uint2 bx = bxl[(ks * 8 + nt) * 32];       // LDS.64 conflict-free
                mma16816(acc[nt], Ah[0], Ah[1], Ah[2], Ah[3], bx.x, bx.y);
                mma16816(acc[nt], Al[0], Al[1], Al[2], Al[3], bx.x, bx.y);
            }
        }

        // ---- 5. activations + state update (thread-local) ----
        // gate qg of unit uu: nt = 2*qg + (uu>>1), reg = (uu&1) + 2*rh
#pragma unroll
        for (int rh = 0; rh < 2; rh++)
#pragma unroll
            for (int uu = 0; uu < 4; uu++) {
                const int nth = uu >> 1, rg = (uu & 1) + 2 * rh;
                float gi = acc[0 + nth][rg];
                float gf = acc[2 + nth][rg];
                float gg = acc[4 + nth][rg];
                float go = acc[6 + nth][rg];
                float ig = fast_sig(gi), fg = fast_sig(gf);
                float g2 = fast_tanh(gg), og = fast_sig(go);
                float cn = fg * c[rh][uu] + ig * g2;
                c[rh][uu] = cn;
                h[rh][uu] = og * fast_tanh(cn);
            }
        __syncwarp();   // all lanes done with ldsm before next step's STS
    }

    // ---- fc head: reduce over the 4 j-lanes of each row ----
    {
        float2 f0 = *(const float2*)(s_fcw + 2 * j);
        float2 f1 = *(const float2*)(s_fcw + 8 + 2 * j);
        float fb = s_fcb;
#pragma unroll
        for (int rh = 0; rh < 2; rh++) {
            float p = h[rh][0] * f0.x + h[rh][1] * f0.y +
                      h[rh][2] * f1.x + h[rh][3] * f1.y;
            p += __shfl_xor_sync(0xffffffffu, p, 1);
            p += __shfl_xor_sync(0xffffffffu, p, 2);
            if (j == 0) {
                int row = rowbase + rh * 8 + g;
                if (row < batch) out[row] = p + fb;
            }
        }
    }
}

extern "C" void kernel_launch(void* const* d_in, const int* in_sizes, int n_in,
                              void* d_out, int out_size)
{
    const float* x   = (const float*)d_in[0];
    const float* Wih = (const float*)d_in[1];
    const float* Whh = (const float*)d_in[2];
    const float* bih = (const float*)d_in[3];
    const float* bhh = (const float*)d_in[4];
    const float* fcw = (const float*)d_in[5];
    const float* fcb = (const float*)d_in[6];
    float* out = (float*)d_out;

    int batch = in_sizes[0] / (SEQT * INS);
    int blocks = (batch + TILE_B - 1) / TILE_B;
    lstm_mma4_kernel<<<blocks, 128>>>(x, Wih, Whh, bih, bhh, fcw, fcb,
                                      out, batch);
}

// round 14
// speedup vs baseline: 6.6155x; 1.2218x over previous
#include <cuda_runtime.h>
#include <cstdint>

#define HID   16
#define INS   64
#define SEQT  12
#define RW    16           // rows per warp
#define NWARP 4
#define TILE_B (RW * NWARP)
#define XSTR  144          // padded stage row stride (bytes), conflict-free
#define WSTAGE (2 * RW * XSTR)   // per-warp stage (hi+lo planes) = 4608

__device__ __forceinline__ uint32_t s2u(const void* p) {
    uint32_t a;
    asm("{ .reg .u64 t; cvta.to.shared.u64 t, %1; cvt.u32.u64 %0, t; }"
        : "=r"(a) : "l"(p));
    return a;
}
// split-fp16: (x0,x1) -> hi pack {lo16=f16(x0), hi16=f16(x1)} + residual pack
__device__ __forceinline__ void packsplit(uint32_t& hp, uint32_t& lp,
                                          float x0, float x1) {
    asm("cvt.rn.f16x2.f32 %0, %1, %2;" : "=r"(hp) : "f"(x1), "f"(x0));
    float f0, f1;
    asm("{.reg .f16 l, h; mov.b32 {l, h}, %2; cvt.f32.f16 %0, l; cvt.f32.f16 %1, h;}"
        : "=f"(f0), "=f"(f1) : "r"(hp));
    asm("cvt.rn.f16x2.f32 %0, %1, %2;" : "=r"(lp) : "f"(x1 - f1), "f"(x0 - f0));
}
// hi-only pack (for weights; residual intentionally dropped -> 2-pass scheme)
__device__ __forceinline__ uint32_t packh(float x0, float x1) {
    uint32_t u;
    asm("cvt.rn.f16x2.f32 %0, %1, %2;" : "=r"(u) : "f"(x1), "f"(x0));
    return u;
}
__device__ __forceinline__ void ldsm4(uint32_t& r0, uint32_t& r1, uint32_t& r2,
                                      uint32_t& r3, uint32_t addr) {
    asm volatile("ldmatrix.sync.aligned.m8n8.x4.shared.b16 {%0,%1,%2,%3}, [%4];"
                 : "=r"(r0), "=r"(r1), "=r"(r2), "=r"(r3) : "r"(addr));
}
__device__ __forceinline__ void mma16816(float* c, uint32_t a0, uint32_t a1,
                                         uint32_t a2, uint32_t a3,
                                         uint32_t b0, uint32_t b1) {
    asm volatile(
        "mma.sync.aligned.m16n8k16.row.col.f32.f16.f16.f32 "
        "{%0,%1,%2,%3}, {%4,%5,%6,%7}, {%8,%9}, {%0,%1,%2,%3};"
        : "+f"(c[0]), "+f"(c[1]), "+f"(c[2]), "+f"(c[3])
        : "r"(a0), "r"(a1), "r"(a2), "r"(a3), "r"(b0), "r"(b1));
}
// single-MUFU activations: tanh.approx (sm_75+); sigmoid via tanh identity
__device__ __forceinline__ float tf_(float x) {
    float y;
    asm("tanh.approx.f32 %0, %1;" : "=f"(y) : "f"(x));
    return y;
}
__device__ __forceinline__ float sg_(float x) {
    return fmaf(0.5f, tf_(0.5f * x), 0.5f);
}

__global__ __launch_bounds__(128, 4)
void lstm_mma5_kernel(const float* __restrict__ x,
                      const float* __restrict__ Wih,   // [64][64]
                      const float* __restrict__ Whh,   // [64][16]
                      const float* __restrict__ bih,
                      const float* __restrict__ bhh,
                      const float* __restrict__ fcw,   // [16]
                      const float* __restrict__ fcb,
                      float* __restrict__ out,
                      int batch)
{
    __shared__ __align__(16) char  s_x[NWARP * WSTAGE];   // per-warp hi+lo planes
    __shared__ __align__(16) uint2 s_bx[4 * 8 * 32];      // Wih frags/lane: 8KB
    __shared__ __align__(16) uint2 s_bhh[8 * 32];         // Whh frags/lane: 2KB
    __shared__ __align__(16) float s_bias[64];
    __shared__ __align__(16) float s_fcw[HID];
    __shared__ float s_fcb;

    const int tid  = threadIdx.x;
    const int lane = tid & 31, warp = tid >> 5;
    const int g = lane >> 2, j = lane & 3;

    if (tid < 64)  s_bias[tid] = bih[tid] + bhh[tid];
    if (tid < HID) s_fcw[tid]  = fcw[tid];
    if (tid == 0)  s_fcb       = fcb[0];

    // ---- pre-pack W fragments (hi plane) into smem; lane-indexed, identical
    //      across warps: warp 0 fills Wih, warp 1 fills Whh ----
    if (warp == 0) {
#pragma unroll
        for (int ks = 0; ks < 4; ks++)
#pragma unroll
            for (int nt = 0; nt < 8; nt++) {
                const float2* p =
                    (const float2*)(Wih + (8 * nt + g) * INS + 16 * ks + 2 * j);
                float2 w0 = __ldg(p);        // k = 2j, 2j+1
                float2 w1 = __ldg(p + 4);    // k = 8+2j, 8+2j+1
                s_bx[(ks * 8 + nt) * 32 + lane] =
                    make_uint2(packh(w0.x, w0.y), packh(w1.x, w1.y));
            }
    } else if (warp == 1) {
#pragma unroll
        for (int nt = 0; nt < 8; nt++) {
            const float2* p = (const float2*)(Whh + (8 * nt + g) * HID + 2 * j);
            float2 w0 = __ldg(p);
            float2 w1 = __ldg(p + 4);
            s_bhh[nt * 32 + lane] =
                make_uint2(packh(w0.x, w0.y), packh(w1.x, w1.y));
        }
    }
    __syncthreads();

    int rowbase = blockIdx.x * TILE_B + warp * RW;
    if (rowbase + RW > batch) rowbase = batch >= RW ? batch - RW : 0;

    // ---- coalesced x staging: lanes 0-15 = even rows, 16-31 = odd rows ----
    const int half = lane >> 4, q = lane & 15;
    const float* xb = x + (size_t)(rowbase + half) * (SEQT * INS) + q * 4;
    char* hs = s_x + warp * WSTAGE + half * XSTR + q * 8;
    char* ls = hs + RW * XSTR;

    // ldmatrix fragment addresses
    const int mrow = lane & 7, msel = lane >> 3;
    const uint32_t smb = s2u(s_x);
    const uint32_t a_hi = smb + warp * WSTAGE +
        ((msel & 1) * 8 + mrow) * XSTR + (msel >> 1) * 16;
    const uint32_t a_lo = a_hi + RW * XSTR;
    const uint2* bxl  = s_bx  + lane;
    const uint2* bhhl = s_bhh + lane;

    // state: h/c [row-half rh][unit uu]; units {2j,2j+1,8+2j,8+2j+1}
    float h[2][4], c[2][4];
#pragma unroll
    for (int rh = 0; rh < 2; rh++)
#pragma unroll
        for (int u = 0; u < 4; u++) { h[rh][u] = 0.f; c[rh][u] = 0.f; }

    // ---- register-carried x prefetch (software pipeline over t) ----
    float4 xf[8];
#pragma unroll
    for (int i = 0; i < 8; i++)
        xf[i] = __ldg((const float4*)(xb + i * (2 * SEQT * INS)));

#pragma unroll 1
    for (int t = 0; t < SEQT; t++) {
        // ---- 1. convert carried x + stage to smem ----
#pragma unroll
        for (int i = 0; i < 8; i++) {
            uint2 H, L;
            packsplit(H.x, L.x, xf[i].x, xf[i].y);
            packsplit(H.y, L.y, xf[i].z, xf[i].w);
            *(uint2*)(hs + i * (2 * XSTR)) = H;
            *(uint2*)(ls + i * (2 * XSTR)) = L;
        }

        // ---- 2. prefetch next step's x (latency covered by mma below) ----
        {
            const int tn = t + 1 < SEQT ? t + 1 : t;
            const float* xt = xb + tn * INS;
#pragma unroll
            for (int i = 0; i < 8; i++)
                xf[i] = __ldg((const float4*)(xt + i * (2 * SEQT * INS)));
        }

        // ---- 3. acc init from bias ----
        float acc[8][4];
#pragma unroll
        for (int nt = 0; nt < 8; nt++) {
            float2 bv = *(const float2*)(s_bias + 8 * nt + 2 * j);
            acc[nt][0] = bv.x; acc[nt][1] = bv.y;
            acc[nt][2] = bv.x; acc[nt][3] = bv.y;
        }

        // ---- 4. recurrence: gates += h @ Whh^T (2-pass split) ----
        //      (also covers the STS->ldmatrix distance)
        if (t > 0) {
            uint32_t ah[4], al[4];
            packsplit(ah[0], al[0], h[0][0], h[0][1]);
            packsplit(ah[1], al[1], h[1][0], h[1][1]);
            packsplit(ah[2], al[2], h[0][2], h[0][3]);
            packsplit(ah[3], al[3], h[1][2], h[1][3]);
#pragma unroll
            for (int nt = 0; nt < 8; nt++) {
                uint2 bh = bhhl[nt * 32];
                mma16816(acc[nt], ah[0], ah[1], ah[2], ah[3], bh.x, bh.y);
                mma16816(acc[nt], al[0], al[1], al[2], al[3], bh.x, bh.y);
            }
        }
        __syncwarp();

        // ---- 5. x-GEMM: gates += x @ Wih^T (2-pass, B frags from smem) ----
#pragma unroll
        for (int ks = 0; ks < 4; ks++) {
            uint32_t Ah[4], Al[4];
            ldsm4(Ah[0], Ah[1], Ah[2], Ah[3], a_hi + ks * 32);
            ldsm4(Al[0], Al[1], Al[2], Al[3], a_lo + ks * 32);
#pragma unroll
            for (int nt = 0; nt < 8; nt++) {
                uint2 bx = bxl[(ks * 8 + nt) * 32];       // LDS.64 conflict-free
                mma16816(acc[nt], Ah[0], Ah[1], Ah[2], Ah[3], bx.x, bx.y);
                mma16816(acc[nt], Al[0], Al[1], Al[2], Al[3], bx.x, bx.y);
            }
        }

        // ---- 6. activations + state update (single-MUFU tanh.approx) ----
        // gate qg of unit uu: nt = 2*qg + (uu>>1), reg = (uu&1) + 2*rh
#pragma unroll
        for (int rh = 0; rh < 2; rh++)
#pragma unroll
            for (int uu = 0; uu < 4; uu++) {
                const int nth = uu >> 1, rg = (uu & 1) + 2 * rh;
                float gi = acc[0 + nth][rg];
                float gf = acc[2 + nth][rg];
                float gg = acc[4 + nth][rg];
                float go = acc[6 + nth][rg];
                float ig = sg_(gi), fg = sg_(gf);
                float g2 = tf_(gg), og = sg_(go);
                float cn = fg * c[rh][uu] + ig * g2;
                c[rh][uu] = cn;
                h[rh][uu] = og * tf_(cn);
            }
        __syncwarp();   // all lanes done with ldsm before next step's STS
    }

    // ---- fc head: reduce over the 4 j-lanes of each row ----
    {
        float2 f0 = *(const float2*)(s_fcw + 2 * j);
        float2 f1 = *(const float2*)(s_fcw + 8 + 2 * j);
        float fb = s_fcb;
#pragma unroll
        for (int rh = 0; rh < 2; rh++) {
            float p = h[rh][0] * f0.x + h[rh][1] * f0.y +
                      h[rh][2] * f1.x + h[rh][3] * f1.y;
            p += __shfl_xor_sync(0xffffffffu, p, 1);
            p += __shfl_xor_sync(0xffffffffu, p, 2);
            if (j == 0) {
                int row = rowbase + rh * 8 + g;
                if (row < batch) out[row] = p + fb;
            }
        }
    }
}

extern "C" void kernel_launch(void* const* d_in, const int* in_sizes, int n_in,
                              void* d_out, int out_size)
{
    const float* x   = (const float*)d_in[0];
    const float* Wih = (const float*)d_in[1];
    const float* Whh = (const float*)d_in[2];
    const float* bih = (const float*)d_in[3];
    const float* bhh = (const float*)d_in[4];
    const float* fcw = (const float*)d_in[5];
    const float* fcb = (const float*)d_in[6];
    float* out = (float*)d_out;

    int batch = in_sizes[0] / (SEQT * INS);
    int blocks = (batch + TILE_B - 1) / TILE_B;
    lstm_mma5_kernel<<<blocks, 128>>>(x, Wih, Whh, bih, bhh, fcw, fcb,
                                      out, batch);
}

// round 15
// speedup vs baseline: 8.3620x; 1.2640x over previous
#include <cuda_runtime.h>
#include <cstdint>

#define HID   16
#define INS   64
#define SEQT  12
#define RW    16           // rows per warp
#define NWARP 4
#define TILE_B (RW * NWARP)
#define XSTR  144          // padded stage row stride (bytes), conflict-free
#define WSTAGE (RW * XSTR) // per-warp stage (hi plane only) = 2304

__device__ __forceinline__ uint32_t s2u(const void* p) {
    uint32_t a;
    asm("{ .reg .u64 t; cvta.to.shared.u64 t, %1; cvt.u32.u64 %0, t; }"
        : "=r"(a) : "l"(p));
    return a;
}
// split-fp16: (x0,x1) -> hi pack + residual pack (recurrence path only)
__device__ __forceinline__ void packsplit(uint32_t& hp, uint32_t& lp,
                                          float x0, float x1) {
    asm("cvt.rn.f16x2.f32 %0, %1, %2;" : "=r"(hp) : "f"(x1), "f"(x0));
    float f0, f1;
    asm("{.reg .f16 l, h; mov.b32 {l, h}, %2; cvt.f32.f16 %0, l; cvt.f32.f16 %1, h;}"
        : "=f"(f0), "=f"(f1) : "r"(hp));
    asm("cvt.rn.f16x2.f32 %0, %1, %2;" : "=r"(lp) : "f"(x1 - f1), "f"(x0 - f0));
}
// plain fp16x2 pack (x and weights; residuals dropped)
__device__ __forceinline__ uint32_t packh(float x0, float x1) {
    uint32_t u;
    asm("cvt.rn.f16x2.f32 %0, %1, %2;" : "=r"(u) : "f"(x1), "f"(x0));
    return u;
}
__device__ __forceinline__ void ldsm4(uint32_t& r0, uint32_t& r1, uint32_t& r2,
                                      uint32_t& r3, uint32_t addr) {
    asm volatile("ldmatrix.sync.aligned.m8n8.x4.shared.b16 {%0,%1,%2,%3}, [%4];"
                 : "=r"(r0), "=r"(r1), "=r"(r2), "=r"(r3) : "r"(addr));
}
__device__ __forceinline__ void mma16816(float* c, uint32_t a0, uint32_t a1,
                                         uint32_t a2, uint32_t a3,
                                         uint32_t b0, uint32_t b1) {
    asm volatile(
        "mma.sync.aligned.m16n8k16.row.col.f32.f16.f16.f32 "
        "{%0,%1,%2,%3}, {%4,%5,%6,%7}, {%8,%9}, {%0,%1,%2,%3};"
        : "+f"(c[0]), "+f"(c[1]), "+f"(c[2]), "+f"(c[3])
        : "r"(a0), "r"(a1), "r"(a2), "r"(a3), "r"(b0), "r"(b1));
}
// single-MUFU activations (validated: rel_err unchanged at 2.7e-4)
__device__ __forceinline__ float tf_(float x) {
    float y;
    asm("tanh.approx.f32 %0, %1;" : "=f"(y) : "f"(x));
    return y;
}
__device__ __forceinline__ float sg_(float x) {
    return fmaf(0.5f, tf_(0.5f * x), 0.5f);
}

__global__ __launch_bounds__(128, 5)
void lstm_mma6_kernel(const float* __restrict__ x,
                      const float* __restrict__ Wih,   // [64][64]
                      const float* __restrict__ Whh,   // [64][16]
                      const float* __restrict__ bih,
                      const float* __restrict__ bhh,
                      const float* __restrict__ fcw,   // [16]
                      const float* __restrict__ fcb,
                      float* __restrict__ out,
                      int batch)
{
    __shared__ __align__(16) char  s_x[NWARP * WSTAGE];  // hi plane only: 9KB
    __shared__ __align__(16) uint2 s_bx[4 * 8 * 32];     // Wih frags/lane: 8KB
    __shared__ __align__(16) uint2 s_bhh[8 * 32];        // Whh frags/lane: 2KB
    __shared__ __align__(16) float s_bias[64];
    __shared__ __align__(16) float s_fcw[HID];
    __shared__ float s_fcb;

    const int tid  = threadIdx.x;
    const int lane = tid & 31, warp = tid >> 5;
    const int g = lane >> 2, j = lane & 3;

    if (tid < 64)  s_bias[tid] = bih[tid] + bhh[tid];
    if (tid < HID) s_fcw[tid]  = fcw[tid];
    if (tid == 0)  s_fcb       = fcb[0];

    // ---- pre-pack W fragments (hi plane) into smem; lane-indexed, identical
    //      across warps: warp 0 fills Wih, warp 1 fills Whh ----
    if (warp == 0) {
#pragma unroll
        for (int ks = 0; ks < 4; ks++)
#pragma unroll
            for (int nt = 0; nt < 8; nt++) {
                const float2* p =
                    (const float2*)(Wih + (8 * nt + g) * INS + 16 * ks + 2 * j);
                float2 w0 = __ldg(p);        // k = 2j, 2j+1
                float2 w1 = __ldg(p + 4);    // k = 8+2j, 8+2j+1
                s_bx[(ks * 8 + nt) * 32 + lane] =
                    make_uint2(packh(w0.x, w0.y), packh(w1.x, w1.y));
            }
    } else if (warp == 1) {
#pragma unroll
        for (int nt = 0; nt < 8; nt++) {
            const float2* p = (const float2*)(Whh + (8 * nt + g) * HID + 2 * j);
            float2 w0 = __ldg(p);
            float2 w1 = __ldg(p + 4);
            s_bhh[nt * 32 + lane] =
                make_uint2(packh(w0.x, w0.y), packh(w1.x, w1.y));
        }
    }
    __syncthreads();

    int rowbase = blockIdx.x * TILE_B + warp * RW;
    if (rowbase + RW > batch) rowbase = batch >= RW ? batch - RW : 0;

    // ---- coalesced x staging: lanes 0-15 = even rows, 16-31 = odd rows ----
    const int half = lane >> 4, q = lane & 15;
    const float* xb = x + (size_t)(rowbase + half) * (SEQT * INS) + q * 4;
    char* hs = s_x + warp * WSTAGE + half * XSTR + q * 8;

    // ldmatrix fragment addresses
    const int mrow = lane & 7, msel = lane >> 3;
    const uint32_t smb = s2u(s_x);
    const uint32_t a_hi = smb + warp * WSTAGE +
        ((msel & 1) * 8 + mrow) * XSTR + (msel >> 1) * 16;
    const uint2* bxl  = s_bx  + lane;
    const uint2* bhhl = s_bhh + lane;

    // state: h/c [row-half rh][unit uu]; units {2j,2j+1,8+2j,8+2j+1}
    float h[2][4], c[2][4];
#pragma unroll
    for (int rh = 0; rh < 2; rh++)
#pragma unroll
        for (int u = 0; u < 4; u++) { h[rh][u] = 0.f; c[rh][u] = 0.f; }

    // ---- register-carried x prefetch (software pipeline over t) ----
    float4 xf[8];
#pragma unroll
    for (int i = 0; i < 8; i++)
        xf[i] = __ldg((const float4*)(xb + i * (2 * SEQT * INS)));

#pragma unroll 1
    for (int t = 0; t < SEQT; t++) {
        // ---- 1. pack carried x to fp16 + stage (hi plane only) ----
#pragma unroll
        for (int i = 0; i < 8; i++) {
            uint2 H;
            H.x = packh(xf[i].x, xf[i].y);
            H.y = packh(xf[i].z, xf[i].w);
            *(uint2*)(hs + i * (2 * XSTR)) = H;
        }

        // ---- 2. prefetch next step's x (latency covered by mma below) ----
        {
            const int tn = t + 1 < SEQT ? t + 1 : t;
            const float* xt = xb + tn * INS;
#pragma unroll
            for (int i = 0; i < 8; i++)
                xf[i] = __ldg((const float4*)(xt + i * (2 * SEQT * INS)));
        }

        // ---- 3. acc init from bias ----
        float acc[8][4];
#pragma unroll
        for (int nt = 0; nt < 8; nt++) {
            float2 bv = *(const float2*)(s_bias + 8 * nt + 2 * j);
            acc[nt][0] = bv.x; acc[nt][1] = bv.y;
            acc[nt][2] = bv.x; acc[nt][3] = bv.y;
        }

        // ---- 4. recurrence: gates += h @ Whh^T (keep 2-pass split: the
        //      h-error feeds back through all 12 steps; only 16 MMAs) ----
        if (t > 0) {
            uint32_t ah[4], al[4];
            packsplit(ah[0], al[0], h[0][0], h[0][1]);
            packsplit(ah[1], al[1], h[1][0], h[1][1]);
            packsplit(ah[2], al[2], h[0][2], h[0][3]);
            packsplit(ah[3], al[3], h[1][2], h[1][3]);
#pragma unroll
            for (int nt = 0; nt < 8; nt++) {
                uint2 bh = bhhl[nt * 32];
                mma16816(acc[nt], ah[0], ah[1], ah[2], ah[3], bh.x, bh.y);
                mma16816(acc[nt], al[0], al[1], al[2], al[3], bh.x, bh.y);
            }
        }
        __syncwarp();

        // ---- 5. x-GEMM: gates += x @ Wih^T (single hi pass) ----
#pragma unroll
        for (int ks = 0; ks < 4; ks++) {
            uint32_t Ah[4];
            ldsm4(Ah[0], Ah[1], Ah[2], Ah[3], a_hi + ks * 32);
#pragma unroll
            for (int nt = 0; nt < 8; nt++) {
                uint2 bx = bxl[(ks * 8 + nt) * 32];       // LDS.64 conflict-free
                mma16816(acc[nt], Ah[0], Ah[1], Ah[2], Ah[3], bx.x, bx.y);
            }
        }

        // ---- 6. activations + state update ----
        // gate qg of unit uu: nt = 2*qg + (uu>>1), reg = (uu&1) + 2*rh
#pragma unroll
        for (int rh = 0; rh < 2; rh++)
#pragma unroll
            for (int uu = 0; uu < 4; uu++) {
                const int nth = uu >> 1, rg = (uu & 1) + 2 * rh;
                float gi = acc[0 + nth][rg];
                float gf = acc[2 + nth][rg];
                float gg = acc[4 + nth][rg];
                float go = acc[6 + nth][rg];
                float ig = sg_(gi), fg = sg_(gf);
                float g2 = tf_(gg), og = sg_(go);
                float cn = fg * c[rh][uu] + ig * g2;
                c[rh][uu] = cn;
                h[rh][uu] = og * tf_(cn);
            }
        __syncwarp();   // all lanes done with ldsm before next step's STS
    }

    // ---- fc head: reduce over the 4 j-lanes of each row ----
    {
        float2 f0 = *(const float2*)(s_fcw + 2 * j);
        float2 f1 = *(const float2*)(s_fcw + 8 + 2 * j);
        float fb = s_fcb;
#pragma unroll
        for (int rh = 0; rh < 2; rh++) {
            float p = h[rh][0] * f0.x + h[rh][1] * f0.y +
                      h[rh][2] * f1.x + h[rh][3] * f1.y;
            p += __shfl_xor_sync(0xffffffffu, p, 1);
            p += __shfl_xor_sync(0xffffffffu, p, 2);
            if (j == 0) {
                int row = rowbase + rh * 8 + g;
                if (row < batch) out[row] = p + fb;
            }
        }
    }
}

extern "C" void kernel_launch(void* const* d_in, const int* in_sizes, int n_in,
                              void* d_out, int out_size)
{
    const float* x   = (const float*)d_in[0];
    const float* Wih = (const float*)d_in[1];
    const float* Whh = (const float*)d_in[2];
    const float* bih = (const float*)d_in[3];
    const float* bhh = (const float*)d_in[4];
    const float* fcw = (const float*)d_in[5];
    const float* fcb = (const float*)d_in[6];
    float* out = (float*)d_out;

    int batch = in_sizes[0] / (SEQT * INS);
    int blocks = (batch + TILE_B - 1) / TILE_B;
    lstm_mma6_kernel<<<blocks, 128>>>(x, Wih, Whh, bih, bhh, fcw, fcb,
                                      out, batch);
}